// round 14
// baseline (speedup 1.0000x reference)
#include <cuda_runtime.h>
#include <math.h>

#define D_DIM 182
#define H_DIM 218
#define W_DIM 182
#define EMBED_DIM 768
#define REGION_MAX 116

#define TPB 256
#define PPB 64                        // points per block
#define NWARP (TPB / 32)              // 8 warps; each copies 8 rows

// first PERSIST_PTS rows (~84 MB) kept default-cached (L2-resident, never drained);
// the rest are streamed with .cs (evict-first) so they don't thrash the pinned set.
#define PERSIST_PTS 28672

__device__ __forceinline__ void store_row6(float4* dst, int lane, int pt,
                                           float4 v0, float4 v1, float4 v2,
                                           float4 v3, float4 v4, float4 v5) {
    if (pt < PERSIST_PTS) {
        dst[lane]       = v0;
        dst[lane + 32]  = v1;
        dst[lane + 64]  = v2;
        dst[lane + 96]  = v3;
        dst[lane + 128] = v4;
        dst[lane + 160] = v5;
    } else {
        __stcs(dst + lane,       v0);
        __stcs(dst + lane + 32,  v1);
        __stcs(dst + lane + 64,  v2);
        __stcs(dst + lane + 96,  v3);
        __stcs(dst + lane + 128, v4);
        __stcs(dst + lane + 160, v5);
    }
}

__global__ __launch_bounds__(TPB) void fused_kernel(
    const float* __restrict__ centers,   // [total, 3]
    const float* __restrict__ mri,       // [4,4]
    const float* __restrict__ aal,       // [4,4]
    const float* __restrict__ aal_data,  // [D,H,W]
    const float* __restrict__ table,     // [117, 768]
    float* __restrict__ out,             // [total, 768]
    int total)
{
    __shared__ float sM[12];
    __shared__ int sRegion[PPB];

    const int tid = threadIdx.x;
    const int base = blockIdx.x * PPB;

    // ---- Phase 0: thread 0 computes combined transform M = inv(aal)*mri
    if (tid == 0) {
        float a[4][8];
        #pragma unroll
        for (int i = 0; i < 4; i++)
            #pragma unroll
            for (int j = 0; j < 4; j++) {
                a[i][j] = aal[i * 4 + j];
                a[i][j + 4] = (i == j) ? 1.0f : 0.0f;
            }
        #pragma unroll
        for (int c = 0; c < 4; c++) {
            int p = c;
            float best = fabsf(a[c][c]);
            for (int r = c + 1; r < 4; r++) {
                float v = fabsf(a[r][c]);
                if (v > best) { best = v; p = r; }
            }
            if (p != c)
                for (int j = 0; j < 8; j++) { float t = a[c][j]; a[c][j] = a[p][j]; a[p][j] = t; }
            float inv = 1.0f / a[c][c];
            for (int j = 0; j < 8; j++) a[c][j] *= inv;
            for (int r = 0; r < 4; r++) {
                if (r == c) continue;
                float f = a[r][c];
                for (int j = 0; j < 8; j++) a[r][j] -= f * a[c][j];
            }
        }
        #pragma unroll
        for (int i = 0; i < 3; i++)
            #pragma unroll
            for (int j = 0; j < 4; j++) {
                float s = 0.0f;
                #pragma unroll
                for (int k = 0; k < 4; k++) s += a[i][k + 4] * mri[k * 4 + j];
                sM[i * 4 + j] = s;
            }
    }
    __syncthreads();

    // ---- Phase 1: 64 parallel region lookups
    if (tid < PPB) {
        int pt = base + tid;
        int region = 0;
        if (pt < total) {
            float x0 = centers[pt * 3 + 0];
            float y0 = centers[pt * 3 + 1];
            float z0 = centers[pt * 3 + 2];
            float X = sM[0] * x0 + sM[1] * y0 + sM[2]  * z0 + sM[3];
            float Y = sM[4] * x0 + sM[5] * y0 + sM[6]  * z0 + sM[7];
            float Z = sM[8] * x0 + sM[9] * y0 + sM[10] * z0 + sM[11];
            int xi = (int)rintf(X);   // round-half-even, matches jnp.round
            int yi = (int)rintf(Y);
            int zi = (int)rintf(Z);
            bool inb = (xi >= 0) & (xi < D_DIM) & (yi >= 0) & (yi < H_DIM) &
                       (zi >= 0) & (zi < W_DIM);
            int cx = min(max(xi, 0), D_DIM - 1);
            int cy = min(max(yi, 0), H_DIM - 1);
            int cz = min(max(zi, 0), W_DIM - 1);
            int r = (int)__ldg(&aal_data[((size_t)cx * H_DIM + cy) * W_DIM + cz]);
            region = (inb && r >= 0 && r <= REGION_MAX) ? r : 0;
        }
        sRegion[tid] = region;
    }
    __syncthreads();

    // ---- Phase 2: warp w copies rows w, w+8, ..., w+56.
    // Software-pipelined: row i+1's loads issue before row i's stores.
    const int warp = tid >> 5;
    const int lane = tid & 31;

    if (base + PPB <= total) {
        const float4* src = (const float4*)(table + (size_t)sRegion[warp] * EMBED_DIM);
        float4 v0 = __ldg(&src[lane]);
        float4 v1 = __ldg(&src[lane + 32]);
        float4 v2 = __ldg(&src[lane + 64]);
        float4 v3 = __ldg(&src[lane + 96]);
        float4 v4 = __ldg(&src[lane + 128]);
        float4 v5 = __ldg(&src[lane + 160]);

        #pragma unroll
        for (int i = 0; i < PPB / NWARP - 1; i++) {       // 7 pipelined iterations
            const float4* nsrc =
                (const float4*)(table + (size_t)sRegion[warp + (i + 1) * NWARP] * EMBED_DIM);
            float4 w0 = __ldg(&nsrc[lane]);
            float4 w1 = __ldg(&nsrc[lane + 32]);
            float4 w2 = __ldg(&nsrc[lane + 64]);
            float4 w3 = __ldg(&nsrc[lane + 96]);
            float4 w4 = __ldg(&nsrc[lane + 128]);
            float4 w5 = __ldg(&nsrc[lane + 160]);

            int pt = base + warp + i * NWARP;
            float4* dst = (float4*)(out + (size_t)pt * EMBED_DIM);
            store_row6(dst, lane, pt, v0, v1, v2, v3, v4, v5);

            v0 = w0; v1 = w1; v2 = w2; v3 = w3; v4 = w4; v5 = w5;
        }
        int pt = base + warp + (PPB / NWARP - 1) * NWARP;
        float4* dst = (float4*)(out + (size_t)pt * EMBED_DIM);
        store_row6(dst, lane, pt, v0, v1, v2, v3, v4, v5);
    } else {
        // generic tail path
        #pragma unroll
        for (int i = 0; i < PPB / NWARP; i++) {
            int p = warp + i * NWARP;
            int pt = base + p;
            if (pt >= total) break;
            const float4* src = (const float4*)(table + (size_t)sRegion[p] * EMBED_DIM);
            float4* dst = (float4*)(out + (size_t)pt * EMBED_DIM);
            float4 v0 = __ldg(&src[lane]);
            float4 v1 = __ldg(&src[lane + 32]);
            float4 v2 = __ldg(&src[lane + 64]);
            float4 v3 = __ldg(&src[lane + 96]);
            float4 v4 = __ldg(&src[lane + 128]);
            float4 v5 = __ldg(&src[lane + 160]);
            store_row6(dst, lane, pt, v0, v1, v2, v3, v4, v5);
        }
    }
}

extern "C" void kernel_launch(void* const* d_in, const int* in_sizes, int n_in,
                              void* d_out, int out_size) {
    const float* centers = (const float*)d_in[0];
    const float* mri     = (const float*)d_in[1];
    const float* aal     = (const float*)d_in[2];
    const float* atlas   = (const float*)d_in[3];
    const float* table   = (const float*)d_in[4];
    float* out = (float*)d_out;

    int total = in_sizes[0] / 3;
    int blocks = (total + PPB - 1) / PPB;

    fused_kernel<<<blocks, TPB>>>(centers, mri, aal, atlas, table, out, total);
}

// round 15
// speedup vs baseline: 1.0196x; 1.0196x over previous
#include <cuda_runtime.h>
#include <math.h>

#define D_DIM 182
#define H_DIM 218
#define W_DIM 182
#define EMBED_DIM 768
#define REGION_MAX 116

#define TPB 512
#define PPB 128                       // points per block
#define NWARP (TPB / 32)              // 16 warps; each copies 8 rows
#define ROWS_PER_WARP (PPB / NWARP)   // 8

__global__ __launch_bounds__(TPB) void fused_kernel(
    const float* __restrict__ centers,   // [total, 3]
    const float* __restrict__ mri,       // [4,4]
    const float* __restrict__ aal,       // [4,4]
    const float* __restrict__ aal_data,  // [D,H,W]
    const float* __restrict__ table,     // [117, 768]
    float* __restrict__ out,             // [total, 768]
    int total)
{
    __shared__ float sM[12];
    __shared__ int sRegion[PPB];

    const int tid = threadIdx.x;
    const int base = blockIdx.x * PPB;

    // ---- Phase 0: thread 0 computes combined transform M = inv(aal)*mri
    if (tid == 0) {
        float a[4][8];
        #pragma unroll
        for (int i = 0; i < 4; i++)
            #pragma unroll
            for (int j = 0; j < 4; j++) {
                a[i][j] = aal[i * 4 + j];
                a[i][j + 4] = (i == j) ? 1.0f : 0.0f;
            }
        #pragma unroll
        for (int c = 0; c < 4; c++) {
            int p = c;
            float best = fabsf(a[c][c]);
            for (int r = c + 1; r < 4; r++) {
                float v = fabsf(a[r][c]);
                if (v > best) { best = v; p = r; }
            }
            if (p != c)
                for (int j = 0; j < 8; j++) { float t = a[c][j]; a[c][j] = a[p][j]; a[p][j] = t; }
            float inv = 1.0f / a[c][c];
            for (int j = 0; j < 8; j++) a[c][j] *= inv;
            for (int r = 0; r < 4; r++) {
                if (r == c) continue;
                float f = a[r][c];
                for (int j = 0; j < 8; j++) a[r][j] -= f * a[c][j];
            }
        }
        #pragma unroll
        for (int i = 0; i < 3; i++)
            #pragma unroll
            for (int j = 0; j < 4; j++) {
                float s = 0.0f;
                #pragma unroll
                for (int k = 0; k < 4; k++) s += a[i][k + 4] * mri[k * 4 + j];
                sM[i * 4 + j] = s;
            }
    }
    __syncthreads();

    // ---- Phase 1: PPB parallel region lookups
    if (tid < PPB) {
        int pt = base + tid;
        int region = 0;
        if (pt < total) {
            float x0 = centers[pt * 3 + 0];
            float y0 = centers[pt * 3 + 1];
            float z0 = centers[pt * 3 + 2];
            float X = sM[0] * x0 + sM[1] * y0 + sM[2]  * z0 + sM[3];
            float Y = sM[4] * x0 + sM[5] * y0 + sM[6]  * z0 + sM[7];
            float Z = sM[8] * x0 + sM[9] * y0 + sM[10] * z0 + sM[11];
            int xi = (int)rintf(X);   // round-half-even, matches jnp.round
            int yi = (int)rintf(Y);
            int zi = (int)rintf(Z);
            bool inb = (xi >= 0) & (xi < D_DIM) & (yi >= 0) & (yi < H_DIM) &
                       (zi >= 0) & (zi < W_DIM);
            int cx = min(max(xi, 0), D_DIM - 1);
            int cy = min(max(yi, 0), H_DIM - 1);
            int cz = min(max(zi, 0), W_DIM - 1);
            int r = (int)__ldg(&aal_data[((size_t)cx * H_DIM + cy) * W_DIM + cz]);
            region = (inb && r >= 0 && r <= REGION_MAX) ? r : 0;
        }
        sRegion[tid] = region;
    }
    __syncthreads();

    // ---- Phase 2: warp w copies rows w, w+16, ..., w+112.
    // Software-pipelined: row i+1's loads issue before row i's stores,
    // keeping 6 independent LDG.128 continuously in flight per warp.
    const int warp = tid >> 5;
    const int lane = tid & 31;

    if (base + PPB <= total) {
        const float4* src = (const float4*)(table + (size_t)sRegion[warp] * EMBED_DIM);
        float4 v0 = __ldg(&src[lane]);
        float4 v1 = __ldg(&src[lane + 32]);
        float4 v2 = __ldg(&src[lane + 64]);
        float4 v3 = __ldg(&src[lane + 96]);
        float4 v4 = __ldg(&src[lane + 128]);
        float4 v5 = __ldg(&src[lane + 160]);

        #pragma unroll
        for (int i = 0; i < ROWS_PER_WARP - 1; i++) {      // 7 pipelined iterations
            const float4* nsrc =
                (const float4*)(table + (size_t)sRegion[warp + (i + 1) * NWARP] * EMBED_DIM);
            float4 w0 = __ldg(&nsrc[lane]);
            float4 w1 = __ldg(&nsrc[lane + 32]);
            float4 w2 = __ldg(&nsrc[lane + 64]);
            float4 w3 = __ldg(&nsrc[lane + 96]);
            float4 w4 = __ldg(&nsrc[lane + 128]);
            float4 w5 = __ldg(&nsrc[lane + 160]);

            float4* dst = (float4*)(out + (size_t)(base + warp + i * NWARP) * EMBED_DIM);
            dst[lane]       = v0;
            dst[lane + 32]  = v1;
            dst[lane + 64]  = v2;
            dst[lane + 96]  = v3;
            dst[lane + 128] = v4;
            dst[lane + 160] = v5;

            v0 = w0; v1 = w1; v2 = w2; v3 = w3; v4 = w4; v5 = w5;
        }
        float4* dst = (float4*)(out +
            (size_t)(base + warp + (ROWS_PER_WARP - 1) * NWARP) * EMBED_DIM);
        dst[lane]       = v0;
        dst[lane + 32]  = v1;
        dst[lane + 64]  = v2;
        dst[lane + 96]  = v3;
        dst[lane + 128] = v4;
        dst[lane + 160] = v5;
    } else {
        // generic tail path
        #pragma unroll
        for (int i = 0; i < ROWS_PER_WARP; i++) {
            int p = warp + i * NWARP;
            int pt = base + p;
            if (pt >= total) break;
            const float4* src = (const float4*)(table + (size_t)sRegion[p] * EMBED_DIM);
            float4* dst = (float4*)(out + (size_t)pt * EMBED_DIM);
            float4 v0 = __ldg(&src[lane]);
            float4 v1 = __ldg(&src[lane + 32]);
            float4 v2 = __ldg(&src[lane + 64]);
            float4 v3 = __ldg(&src[lane + 96]);
            float4 v4 = __ldg(&src[lane + 128]);
            float4 v5 = __ldg(&src[lane + 160]);
            dst[lane]       = v0;
            dst[lane + 32]  = v1;
            dst[lane + 64]  = v2;
            dst[lane + 96]  = v3;
            dst[lane + 128] = v4;
            dst[lane + 160] = v5;
        }
    }
}

extern "C" void kernel_launch(void* const* d_in, const int* in_sizes, int n_in,
                              void* d_out, int out_size) {
    const float* centers = (const float*)d_in[0];
    const float* mri     = (const float*)d_in[1];
    const float* aal     = (const float*)d_in[2];
    const float* atlas   = (const float*)d_in[3];
    const float* table   = (const float*)d_in[4];
    float* out = (float*)d_out;

    int total = in_sizes[0] / 3;
    int blocks = (total + PPB - 1) / PPB;

    fused_kernel<<<blocks, TPB>>>(centers, mri, aal, atlas, table, out, total);
}

// round 16
// speedup vs baseline: 1.0698x; 1.0493x over previous
#include <cuda_runtime.h>
#include <math.h>

#define D_DIM 182
#define H_DIM 218
#define W_DIM 182
#define EMBED_DIM 768
#define REGION_MAX 116

#define TPB 256
#define PPB 64                        // points per block
#define NWARP (TPB / 32)              // 8 warps; each copies 8 rows

__global__ __launch_bounds__(TPB) void fused_kernel(
    const float* __restrict__ centers,   // [total, 3]
    const float* __restrict__ mri,       // [4,4]
    const float* __restrict__ aal,       // [4,4]
    const float* __restrict__ aal_data,  // [D,H,W]
    const float* __restrict__ table,     // [117, 768]
    float* __restrict__ out,             // [total, 768]
    int total)
{
    __shared__ float sM[12];
    __shared__ int sRegion[PPB];

    const int tid = threadIdx.x;
    const int base = blockIdx.x * PPB;

    // ---- Phase 0: thread 0 computes combined transform M = inv(aal)*mri
    if (tid == 0) {
        float a[4][8];
        #pragma unroll
        for (int i = 0; i < 4; i++)
            #pragma unroll
            for (int j = 0; j < 4; j++) {
                a[i][j] = aal[i * 4 + j];
                a[i][j + 4] = (i == j) ? 1.0f : 0.0f;
            }
        #pragma unroll
        for (int c = 0; c < 4; c++) {
            int p = c;
            float best = fabsf(a[c][c]);
            for (int r = c + 1; r < 4; r++) {
                float v = fabsf(a[r][c]);
                if (v > best) { best = v; p = r; }
            }
            if (p != c)
                for (int j = 0; j < 8; j++) { float t = a[c][j]; a[c][j] = a[p][j]; a[p][j] = t; }
            float inv = 1.0f / a[c][c];
            for (int j = 0; j < 8; j++) a[c][j] *= inv;
            for (int r = 0; r < 4; r++) {
                if (r == c) continue;
                float f = a[r][c];
                for (int j = 0; j < 8; j++) a[r][j] -= f * a[c][j];
            }
        }
        #pragma unroll
        for (int i = 0; i < 3; i++)
            #pragma unroll
            for (int j = 0; j < 4; j++) {
                float s = 0.0f;
                #pragma unroll
                for (int k = 0; k < 4; k++) s += a[i][k + 4] * mri[k * 4 + j];
                sM[i * 4 + j] = s;
            }
    }
    __syncthreads();

    // ---- Phase 1: 64 parallel region lookups
    if (tid < PPB) {
        int pt = base + tid;
        int region = 0;
        if (pt < total) {
            float x0 = centers[pt * 3 + 0];
            float y0 = centers[pt * 3 + 1];
            float z0 = centers[pt * 3 + 2];
            float X = sM[0] * x0 + sM[1] * y0 + sM[2]  * z0 + sM[3];
            float Y = sM[4] * x0 + sM[5] * y0 + sM[6]  * z0 + sM[7];
            float Z = sM[8] * x0 + sM[9] * y0 + sM[10] * z0 + sM[11];
            int xi = (int)rintf(X);   // round-half-even, matches jnp.round
            int yi = (int)rintf(Y);
            int zi = (int)rintf(Z);
            bool inb = (xi >= 0) & (xi < D_DIM) & (yi >= 0) & (yi < H_DIM) &
                       (zi >= 0) & (zi < W_DIM);
            int cx = min(max(xi, 0), D_DIM - 1);
            int cy = min(max(yi, 0), H_DIM - 1);
            int cz = min(max(zi, 0), W_DIM - 1);
            int r = (int)__ldg(&aal_data[((size_t)cx * H_DIM + cy) * W_DIM + cz]);
            region = (inb && r >= 0 && r <= REGION_MAX) ? r : 0;
        }
        sRegion[tid] = region;
    }
    __syncthreads();

    // ---- Phase 2: warp w copies rows w, w+8, ..., w+56.
    // Software-pipelined: row i+1's loads issue before row i's stores,
    // keeping 6 independent LDG.128 continuously in flight per warp.
    const int warp = tid >> 5;
    const int lane = tid & 31;

    if (base + PPB <= total) {
        // full-block fast path (always taken when total % 64 == 0)
        const float4* src = (const float4*)(table + (size_t)sRegion[warp] * EMBED_DIM);
        float4 v0 = __ldg(&src[lane]);
        float4 v1 = __ldg(&src[lane + 32]);
        float4 v2 = __ldg(&src[lane + 64]);
        float4 v3 = __ldg(&src[lane + 96]);
        float4 v4 = __ldg(&src[lane + 128]);
        float4 v5 = __ldg(&src[lane + 160]);

        #pragma unroll
        for (int i = 0; i < PPB / NWARP - 1; i++) {       // 7 pipelined iterations
            const float4* nsrc =
                (const float4*)(table + (size_t)sRegion[warp + (i + 1) * NWARP] * EMBED_DIM);
            float4 w0 = __ldg(&nsrc[lane]);
            float4 w1 = __ldg(&nsrc[lane + 32]);
            float4 w2 = __ldg(&nsrc[lane + 64]);
            float4 w3 = __ldg(&nsrc[lane + 96]);
            float4 w4 = __ldg(&nsrc[lane + 128]);
            float4 w5 = __ldg(&nsrc[lane + 160]);

            float4* dst = (float4*)(out + (size_t)(base + warp + i * NWARP) * EMBED_DIM);
            dst[lane]       = v0;
            dst[lane + 32]  = v1;
            dst[lane + 64]  = v2;
            dst[lane + 96]  = v3;
            dst[lane + 128] = v4;
            dst[lane + 160] = v5;

            v0 = w0; v1 = w1; v2 = w2; v3 = w3; v4 = w4; v5 = w5;
        }
        float4* dst = (float4*)(out +
            (size_t)(base + warp + (PPB / NWARP - 1) * NWARP) * EMBED_DIM);
        dst[lane]       = v0;
        dst[lane + 32]  = v1;
        dst[lane + 64]  = v2;
        dst[lane + 96]  = v3;
        dst[lane + 128] = v4;
        dst[lane + 160] = v5;
    } else {
        // generic tail path
        #pragma unroll
        for (int i = 0; i < PPB / NWARP; i++) {
            int p = warp + i * NWARP;
            int pt = base + p;
            if (pt >= total) break;
            const float4* src = (const float4*)(table + (size_t)sRegion[p] * EMBED_DIM);
            float4* dst = (float4*)(out + (size_t)pt * EMBED_DIM);
            float4 v0 = __ldg(&src[lane]);
            float4 v1 = __ldg(&src[lane + 32]);
            float4 v2 = __ldg(&src[lane + 64]);
            float4 v3 = __ldg(&src[lane + 96]);
            float4 v4 = __ldg(&src[lane + 128]);
            float4 v5 = __ldg(&src[lane + 160]);
            dst[lane]       = v0;
            dst[lane + 32]  = v1;
            dst[lane + 64]  = v2;
            dst[lane + 96]  = v3;
            dst[lane + 128] = v4;
            dst[lane + 160] = v5;
        }
    }
}

extern "C" void kernel_launch(void* const* d_in, const int* in_sizes, int n_in,
                              void* d_out, int out_size) {
    const float* centers = (const float*)d_in[0];
    const float* mri     = (const float*)d_in[1];
    const float* aal     = (const float*)d_in[2];
    const float* atlas   = (const float*)d_in[3];
    const float* table   = (const float*)d_in[4];
    float* out = (float*)d_out;

    int total = in_sizes[0] / 3;
    int blocks = (total + PPB - 1) / PPB;

    fused_kernel<<<blocks, TPB>>>(centers, mri, aal, atlas, table, out, total);
}

// round 17
// speedup vs baseline: 1.0886x; 1.0175x over previous
#include <cuda_runtime.h>
#include <math.h>

#define D_DIM 182
#define H_DIM 218
#define W_DIM 182
#define EMBED_DIM 768
#define REGION_MAX 116

#define TPB 256
#define PPB 64                        // points per block
#define NWARP (TPB / 32)              // 8 warps; each copies 8 rows
#define ROWS_PER_WARP (PPB / NWARP)   // 8

__global__ __launch_bounds__(TPB) void fused_kernel(
    const float* __restrict__ centers,   // [total, 3]
    const float* __restrict__ mri,       // [4,4]
    const float* __restrict__ aal,       // [4,4]
    const float* __restrict__ aal_data,  // [D,H,W]
    const float* __restrict__ table,     // [117, 768]
    float* __restrict__ out,             // [total, 768]
    int total)
{
    __shared__ float sM[12];

    const int tid = threadIdx.x;
    const int base = blockIdx.x * PPB;

    // ---- Phase 0: thread 0 computes combined transform M = inv(aal)*mri
    if (tid == 0) {
        float a[4][8];
        #pragma unroll
        for (int i = 0; i < 4; i++)
            #pragma unroll
            for (int j = 0; j < 4; j++) {
                a[i][j] = aal[i * 4 + j];
                a[i][j + 4] = (i == j) ? 1.0f : 0.0f;
            }
        #pragma unroll
        for (int c = 0; c < 4; c++) {
            int p = c;
            float best = fabsf(a[c][c]);
            for (int r = c + 1; r < 4; r++) {
                float v = fabsf(a[r][c]);
                if (v > best) { best = v; p = r; }
            }
            if (p != c)
                for (int j = 0; j < 8; j++) { float t = a[c][j]; a[c][j] = a[p][j]; a[p][j] = t; }
            float inv = 1.0f / a[c][c];
            for (int j = 0; j < 8; j++) a[c][j] *= inv;
            for (int r = 0; r < 4; r++) {
                if (r == c) continue;
                float f = a[r][c];
                for (int j = 0; j < 8; j++) a[r][j] -= f * a[c][j];
            }
        }
        #pragma unroll
        for (int i = 0; i < 3; i++)
            #pragma unroll
            for (int j = 0; j < 4; j++) {
                float s = 0.0f;
                #pragma unroll
                for (int k = 0; k < 4; k++) s += a[i][k + 4] * mri[k * 4 + j];
                sM[i * 4 + j] = s;
            }
    }
    __syncthreads();

    const int warp = tid >> 5;
    const int lane = tid & 31;

    // ---- Phase 1 (warp-private): lane j (<8) computes region of row warp + j*NWARP.
    // No cross-warp dependency -> no second __syncthreads, no smem round-trip.
    int myRegion = 0;
    if (lane < ROWS_PER_WARP) {
        int pt = base + warp + lane * NWARP;
        if (pt < total) {
            float x0 = centers[pt * 3 + 0];
            float y0 = centers[pt * 3 + 1];
            float z0 = centers[pt * 3 + 2];
            float X = sM[0] * x0 + sM[1] * y0 + sM[2]  * z0 + sM[3];
            float Y = sM[4] * x0 + sM[5] * y0 + sM[6]  * z0 + sM[7];
            float Z = sM[8] * x0 + sM[9] * y0 + sM[10] * z0 + sM[11];
            int xi = (int)rintf(X);   // round-half-even, matches jnp.round
            int yi = (int)rintf(Y);
            int zi = (int)rintf(Z);
            bool inb = (xi >= 0) & (xi < D_DIM) & (yi >= 0) & (yi < H_DIM) &
                       (zi >= 0) & (zi < W_DIM);
            int cx = min(max(xi, 0), D_DIM - 1);
            int cy = min(max(yi, 0), H_DIM - 1);
            int cz = min(max(zi, 0), W_DIM - 1);
            int r = (int)__ldg(&aal_data[((size_t)cx * H_DIM + cy) * W_DIM + cz]);
            myRegion = (inb && r >= 0 && r <= REGION_MAX) ? r : 0;
        }
    }

    // ---- Phase 2: warp w copies rows w, w+8, ..., w+56 (software-pipelined).
    if (base + PPB <= total) {
        // full-block fast path (always taken when total % 64 == 0)
        int rg = __shfl_sync(0xffffffffu, myRegion, 0);
        const float4* src = (const float4*)(table + (size_t)rg * EMBED_DIM);
        float4 v0 = __ldg(&src[lane]);
        float4 v1 = __ldg(&src[lane + 32]);
        float4 v2 = __ldg(&src[lane + 64]);
        float4 v3 = __ldg(&src[lane + 96]);
        float4 v4 = __ldg(&src[lane + 128]);
        float4 v5 = __ldg(&src[lane + 160]);

        #pragma unroll
        for (int i = 0; i < ROWS_PER_WARP - 1; i++) {     // 7 pipelined iterations
            int nrg = __shfl_sync(0xffffffffu, myRegion, i + 1);
            const float4* nsrc = (const float4*)(table + (size_t)nrg * EMBED_DIM);
            float4 w0 = __ldg(&nsrc[lane]);
            float4 w1 = __ldg(&nsrc[lane + 32]);
            float4 w2 = __ldg(&nsrc[lane + 64]);
            float4 w3 = __ldg(&nsrc[lane + 96]);
            float4 w4 = __ldg(&nsrc[lane + 128]);
            float4 w5 = __ldg(&nsrc[lane + 160]);

            float4* dst = (float4*)(out + (size_t)(base + warp + i * NWARP) * EMBED_DIM);
            dst[lane]       = v0;
            dst[lane + 32]  = v1;
            dst[lane + 64]  = v2;
            dst[lane + 96]  = v3;
            dst[lane + 128] = v4;
            dst[lane + 160] = v5;

            v0 = w0; v1 = w1; v2 = w2; v3 = w3; v4 = w4; v5 = w5;
        }
        float4* dst = (float4*)(out +
            (size_t)(base + warp + (ROWS_PER_WARP - 1) * NWARP) * EMBED_DIM);
        dst[lane]       = v0;
        dst[lane + 32]  = v1;
        dst[lane + 64]  = v2;
        dst[lane + 96]  = v3;
        dst[lane + 128] = v4;
        dst[lane + 160] = v5;
    } else {
        // generic tail path
        #pragma unroll
        for (int i = 0; i < ROWS_PER_WARP; i++) {
            int pt = base + warp + i * NWARP;
            if (pt >= total) break;
            int rg = __shfl_sync(0xffffffffu, myRegion, i);
            const float4* src = (const float4*)(table + (size_t)rg * EMBED_DIM);
            float4* dst = (float4*)(out + (size_t)pt * EMBED_DIM);
            float4 v0 = __ldg(&src[lane]);
            float4 v1 = __ldg(&src[lane + 32]);
            float4 v2 = __ldg(&src[lane + 64]);
            float4 v3 = __ldg(&src[lane + 96]);
            float4 v4 = __ldg(&src[lane + 128]);
            float4 v5 = __ldg(&src[lane + 160]);
            dst[lane]       = v0;
            dst[lane + 32]  = v1;
            dst[lane + 64]  = v2;
            dst[lane + 96]  = v3;
            dst[lane + 128] = v4;
            dst[lane + 160] = v5;
        }
    }
}

extern "C" void kernel_launch(void* const* d_in, const int* in_sizes, int n_in,
                              void* d_out, int out_size) {
    const float* centers = (const float*)d_in[0];
    const float* mri     = (const float*)d_in[1];
    const float* aal     = (const float*)d_in[2];
    const float* atlas   = (const float*)d_in[3];
    const float* table   = (const float*)d_in[4];
    float* out = (float*)d_out;

    int total = in_sizes[0] / 3;
    int blocks = (total + PPB - 1) / PPB;

    fused_kernel<<<blocks, TPB>>>(centers, mri, aal, atlas, table, out, total);
}